// round 1
// baseline (speedup 1.0000x reference)
#include <cuda_runtime.h>
#include <cstdint>
#include <cstddef>

typedef unsigned long long ull;

#define T_LEN 2048
#define B_SZ  128
#define HID   64
#define G3    192
#define NCLS  20

// 402 MB scratch for precomputed input projections xg[d][b][t][g]
__device__ float g_xg[(size_t)2 * B_SZ * T_LEN * G3];
// pooled features [b][256] = [mean_f, mean_b, max_f, max_b]
__device__ float g_feats[B_SZ * 256];

// ---------- packed f32x2 + fast-math helpers ----------
__device__ __forceinline__ void ffma2(ull& d, ull a, ull b) {
    asm("fma.rn.f32x2 %0, %1, %2, %0;" : "+l"(d) : "l"(a), "l"(b));
}
__device__ __forceinline__ ull fadd2(ull a, ull b) {
    ull r; asm("add.rn.f32x2 %0, %1, %2;" : "=l"(r) : "l"(a), "l"(b)); return r;
}
__device__ __forceinline__ void upk2(ull v, float& lo, float& hi) {
    asm("mov.b64 {%0, %1}, %2;" : "=f"(lo), "=f"(hi) : "l"(v));
}
__device__ __forceinline__ float ex2a(float x) {
    float r; asm("ex2.approx.f32 %0, %1;" : "=f"(r) : "f"(x)); return r;
}
__device__ __forceinline__ float rcpa(float x) {
    float r; asm("rcp.approx.f32 %0, %1;" : "=f"(r) : "f"(x)); return r;
}
// sigmoid(p) = 1/(1+exp(-p)); exp via ex2 (err ~1e-6 rel)
__device__ __forceinline__ float sigm(float p) {
    return rcpa(1.0f + ex2a(-1.4426950408889634f * p));
}
// tanh(x) = 1 - 2/(1+exp(2x)); exact form, ~1e-6 err (NOT tanh.approx)
__device__ __forceinline__ float tanh_fast(float x) {
    return 1.0f - 2.0f * rcpa(1.0f + ex2a(2.8853900817779268f * x));
}

// =====================================================================
// Kernel A: xg[d][b][t][g] = emb[tok(d,t)] @ wih_d^T + bih_d   (fp32)
// Block: one (d, b, 64-timestep tile). 256 threads = 8 warps.
// warp = t-group (8 t each), lane covers g = lane + 32q, q<6.
// f32x2 packing over the K dimension (pairs of e-indices).
// =====================================================================
__global__ void __launch_bounds__(256) kA(
    const int*   __restrict__ tokens,
    const float* __restrict__ emb,
    const float* __restrict__ wih_f, const float* __restrict__ bih_f,
    const float* __restrict__ wih_b, const float* __restrict__ bih_b)
{
    extern __shared__ float smem[];
    float2* xsh = (float2*)smem;                   // [t][k2]: t*32 + k2   (64x32)
    float2* wsh = (float2*)(smem + 4096);          // [k2][g]: k2*193 + g  (padded)
    float*  bsh = smem + 4096 + 32 * 193 * 2;      // [192]

    const int d  = blockIdx.z;
    const int b  = blockIdx.y;
    const int t0 = blockIdx.x * 64;
    const float* wih = d ? wih_b : wih_f;
    const float* bih = d ? bih_b : bih_f;
    const int tid = threadIdx.x;

    // stage weights: wsh[k2][g] = (wih[g][2k2], wih[g][2k2+1])
    for (int idx = tid; idx < 192 * 32; idx += 256) {
        int g = idx >> 5, k2 = idx & 31;
        wsh[k2 * 193 + g] = ((const float2*)(wih + g * 64))[k2];
    }
    if (tid < 192) bsh[tid] = bih[tid];
    // stage x tile via embedding gather (time reversed for backward dir)
    for (int idx = tid; idx < 64 * 32; idx += 256) {
        int t = idx >> 5, k2 = idx & 31;
        int tt  = t0 + t;
        int tok = tokens[b * T_LEN + (d ? (T_LEN - 1 - tt) : tt)];
        xsh[t * 32 + k2] = ((const float2*)(emb + (size_t)tok * 64))[k2];
    }
    __syncthreads();

    const int lane = tid & 31;
    const int wrp  = tid >> 5;

    ull acc[8][6];
#pragma unroll
    for (int i = 0; i < 8; i++)
#pragma unroll
        for (int q = 0; q < 6; q++) acc[i][q] = 0ULL;

    const ull* xp = (const ull*)xsh;
    const ull* wp = (const ull*)wsh;

#pragma unroll 2
    for (int k2 = 0; k2 < 32; k2++) {
        ull xs[8], ws[6];
#pragma unroll
        for (int i = 0; i < 8; i++) xs[i] = xp[(wrp * 8 + i) * 32 + k2];  // broadcast
#pragma unroll
        for (int q = 0; q < 6; q++) ws[q] = wp[k2 * 193 + lane + 32 * q]; // coalesced
#pragma unroll
        for (int i = 0; i < 8; i++)
#pragma unroll
            for (int q = 0; q < 6; q++) ffma2(acc[i][q], xs[i], ws[q]);
    }

    float* out_base = g_xg + (((size_t)d * B_SZ + b) * T_LEN + t0) * G3;
#pragma unroll
    for (int i = 0; i < 8; i++) {
        int t = wrp * 8 + i;
#pragma unroll
        for (int q = 0; q < 6; q++) {
            int g = lane + 32 * q;
            float lo, hi; upk2(acc[i][q], lo, hi);
            out_base[(size_t)t * G3 + g] = lo + hi + bsh[g];
        }
    }
}

// =====================================================================
// Kernel B: the GRU recurrence + on-the-fly mean/max pooling.
// 128 blocks: (direction, batch-pair). 384 threads: (bb in {0,1}, j in [0,192)).
// Thread j holds whh row j in 32 packed-f32x2 registers; per step a
// 64-length dot with h from shared (LDS.128, broadcast within warp).
// Gate order r,z,n. Threads j>=128 do the gating + pooling.
// =====================================================================
__global__ void __launch_bounds__(384) kB(
    const float* __restrict__ whh_f, const float* __restrict__ bhh_f,
    const float* __restrict__ whh_b, const float* __restrict__ bhh_b)
{
    __shared__ __align__(16) float h_sh[2][64];
    __shared__ float sg_sh[2][128];   // sigmoid(r), sigmoid(z)

    const int tid  = threadIdx.x;
    const int bb   = tid / 192;
    const int j    = tid % 192;
    const int d    = blockIdx.x >> 6;
    const int pair = blockIdx.x & 63;
    const int b    = pair * 2 + bb;

    const float* whh = d ? whh_b : whh_f;
    const float* bhh = d ? bhh_b : bhh_f;

    ull w2[32];
#pragma unroll
    for (int i = 0; i < 32; i++) w2[i] = ((const ull*)(whh + j * 64))[i];
    const float bj = bhh[j];

    if (tid < 128) h_sh[tid >> 6][tid & 63] = 0.0f;

    const float* xp  = g_xg + (((size_t)d * B_SZ + b) * T_LEN) * G3 + j;
    float xg0 = xp[0];
    float xg1 = xp[G3];
    const float* xpn = xp + 2 * G3;   // prefetch cursor (t+2)

    float sum = 0.0f, mx = -1e30f;
    __syncthreads();

    for (int t = 0; t < T_LEN; t++) {
        // ---- matvec: hg[j] = whh[j,:] . h + bhh[j] ----
        ull a0 = 0ULL, a1 = 0ULL;
        const ulonglong2* h2 = (const ulonglong2*)(h_sh[bb]);
#pragma unroll
        for (int i = 0; i < 16; i++) {
            ulonglong2 hv = h2[i];
            ffma2(a0, w2[2 * i],     hv.x);
            ffma2(a1, w2[2 * i + 1], hv.y);
        }
        float lo, hi; upk2(fadd2(a0, a1), lo, hi);
        const float hg = lo + hi + bj;
        const float xg = xg0;

        // rotate prefetch pipeline (2 steps ahead)
        xg0 = xg1;
        if (t + 2 < T_LEN) xg1 = *xpn;
        xpn += G3;

        if (j < 128) sg_sh[bb][j] = sigm(xg + hg);   // r (j<64) and z (64<=j<128)
        __syncthreads();

        if (j >= 128) {                               // n-gate threads do the update
            const int k = j - 128;
            const float r     = sg_sh[bb][k];
            const float z     = sg_sh[bb][64 + k];
            const float hprev = h_sh[bb][k];
            const float n  = tanh_fast(xg + r * hg);  // hg here = hn (incl. bhh_n)
            const float hn = (1.0f - z) * n + z * hprev;
            h_sh[bb][k] = hn;
            sum += hn;
            mx = fmaxf(mx, hn);
        }
        __syncthreads();
    }

    if (j >= 128) {
        const int k = j - 128;
        float* f = g_feats + b * 256;
        if (d == 0) { f[k]      = sum * (1.0f / T_LEN); f[128 + k] = mx; }
        else        { f[64 + k] = sum * (1.0f / T_LEN); f[192 + k] = mx; }
    }
}

// =====================================================================
// Kernel C: classifier head. block = batch row, 64 threads.
// hid = gelu_exact(feats @ w1^T + b1); out = hid @ w2^T + b2
// =====================================================================
__global__ void __launch_bounds__(64) kC(
    const float* __restrict__ w1, const float* __restrict__ b1,
    const float* __restrict__ w2, const float* __restrict__ b2,
    float* __restrict__ out)
{
    const int b = blockIdx.x;
    const int j = threadIdx.x;
    __shared__ float hid[64];

    const float* f  = g_feats + b * 256;
    const float* wr = w1 + j * 256;
    float acc = b1[j];
#pragma unroll 8
    for (int i = 0; i < 256; i++) acc += f[i] * wr[i];
    // exact GELU (approximate=False): 0.5*x*(1+erf(x/sqrt(2)))
    hid[j] = 0.5f * acc * (1.0f + erff(acc * 0.70710678118654752f));
    __syncthreads();

    if (j < NCLS) {
        const float* w2r = w2 + j * 64;
        float o = b2[j];
#pragma unroll
        for (int i = 0; i < 64; i++) o += hid[i] * w2r[i];
        out[b * NCLS + j] = o;
    }
}

// =====================================================================
extern "C" void kernel_launch(void* const* d_in, const int* in_sizes, int n_in,
                              void* d_out, int out_size)
{
    const int*   tokens = (const int*)  d_in[0];
    const float* emb    = (const float*)d_in[1];
    const float* wih_f  = (const float*)d_in[2];
    const float* whh_f  = (const float*)d_in[3];
    const float* bih_f  = (const float*)d_in[4];
    const float* bhh_f  = (const float*)d_in[5];
    const float* wih_b  = (const float*)d_in[6];
    const float* whh_b  = (const float*)d_in[7];
    const float* bih_b  = (const float*)d_in[8];
    const float* bhh_b  = (const float*)d_in[9];
    const float* w1     = (const float*)d_in[10];
    const float* b1     = (const float*)d_in[11];
    const float* w2     = (const float*)d_in[12];
    const float* b2     = (const float*)d_in[13];
    float* out = (float*)d_out;

    const size_t smemA = (size_t)(4096 + 32 * 193 * 2 + 192) * sizeof(float); // 66560 B
    cudaFuncSetAttribute(kA, cudaFuncAttributeMaxDynamicSharedMemorySize, (int)smemA);

    kA<<<dim3(32, 128, 2), 256, smemA>>>(tokens, emb, wih_f, bih_f, wih_b, bih_b);
    kB<<<128, 384>>>(whh_f, bhh_f, whh_b, bhh_b);
    kC<<<128, 64>>>(w1, b1, w2, b2, out);
}

// round 2
// speedup vs baseline: 1.5415x; 1.5415x over previous
#include <cuda_runtime.h>
#include <cstdint>
#include <cstddef>

typedef unsigned long long ull;

#define T_LEN 2048
#define B_SZ  128
#define HID   64
#define G3    192
#define NCLS  20
#define VOCAB 50257

// per-vocab input projections: proj[v][d*192+g] = emb[v] . wih_d[g] + bih_d[g]
__device__ float g_proj[(size_t)VOCAB * 384];
// pooled features [b][256] = [mean_f, mean_b, max_f, max_b]
__device__ float g_feats[B_SZ * 256];

// ---------- packed f32x2 + fast-math helpers ----------
__device__ __forceinline__ void ffma2(ull& d, ull a, ull b) {
    asm("fma.rn.f32x2 %0, %1, %2, %0;" : "+l"(d) : "l"(a), "l"(b));
}
__device__ __forceinline__ ull fadd2(ull a, ull b) {
    ull r; asm("add.rn.f32x2 %0, %1, %2;" : "=l"(r) : "l"(a), "l"(b)); return r;
}
__device__ __forceinline__ void upk2(ull v, float& lo, float& hi) {
    asm("mov.b64 {%0, %1}, %2;" : "=f"(lo), "=f"(hi) : "l"(v));
}
__device__ __forceinline__ float ex2a(float x) {
    float r; asm("ex2.approx.f32 %0, %1;" : "=f"(r) : "f"(x)); return r;
}
__device__ __forceinline__ float rcpa(float x) {
    float r; asm("rcp.approx.f32 %0, %1;" : "=f"(r) : "f"(x)); return r;
}
__device__ __forceinline__ float sigm(float p) {
    return rcpa(1.0f + ex2a(-1.4426950408889634f * p));
}
__device__ __forceinline__ float tanh_fast(float x) {
    return 1.0f - 2.0f * rcpa(1.0f + ex2a(2.8853900817779268f * x));
}

// =====================================================================
// Kernel A2: vocab projection table.
// proj[v][dg] for dg in [0,384): dg<192 -> forward wih/bih, else backward.
// Block: 64 vocab rows x 96 dg columns. 256 threads (8 warps):
// warp = 8 v-rows, lane covers g = lane + 32q (q<3). f32x2 over K.
// =====================================================================
__global__ void __launch_bounds__(256) kA2(
    const float* __restrict__ emb,
    const float* __restrict__ wih_f, const float* __restrict__ bih_f,
    const float* __restrict__ wih_b, const float* __restrict__ bih_b)
{
    __shared__ float2 xsh[64][32];   // [v_local][k2]
    __shared__ float2 wsh[32][97];   // [k2][g_local] padded
    __shared__ float  bsh[96];

    const int vt  = blockIdx.x;        // vocab tile (64 rows)
    const int dg0 = blockIdx.y * 96;   // dg quarter
    const int tid = threadIdx.x;

    // stage weights + bias for 96 dg rows
    for (int idx = tid; idx < 96 * 32; idx += 256) {
        int g = idx >> 5, k2 = idx & 31;
        int dg = dg0 + g;
        const float2* src = (dg < 192) ? (const float2*)(wih_f + dg * 64)
                                       : (const float2*)(wih_b + (dg - 192) * 64);
        wsh[k2][g] = src[k2];
    }
    if (tid < 96) {
        int dg = dg0 + tid;
        bsh[tid] = (dg < 192) ? bih_f[dg] : bih_b[dg - 192];
    }
    // stage 64 embedding rows (clamped at vocab tail)
    for (int idx = tid; idx < 64 * 32; idx += 256) {
        int vl = idx >> 5, k2 = idx & 31;
        int v = vt * 64 + vl; if (v >= VOCAB) v = VOCAB - 1;
        xsh[vl][k2] = ((const float2*)(emb + (size_t)v * 64))[k2];
    }
    __syncthreads();

    const int lane = tid & 31;
    const int wrp  = tid >> 5;

    ull acc[8][3];
#pragma unroll
    for (int i = 0; i < 8; i++)
#pragma unroll
        for (int q = 0; q < 3; q++) acc[i][q] = 0ULL;

    const ull* xp = (const ull*)xsh;
    const ull* wp = (const ull*)wsh;

#pragma unroll 4
    for (int k2 = 0; k2 < 32; k2++) {
        ull xs[8], ws[3];
#pragma unroll
        for (int i = 0; i < 8; i++) xs[i] = xp[(wrp * 8 + i) * 32 + k2];
#pragma unroll
        for (int q = 0; q < 3; q++) ws[q] = wp[k2 * 97 + lane + 32 * q];
#pragma unroll
        for (int i = 0; i < 8; i++)
#pragma unroll
            for (int q = 0; q < 3; q++) ffma2(acc[i][q], xs[i], ws[q]);
    }

#pragma unroll
    for (int i = 0; i < 8; i++) {
        int v = vt * 64 + wrp * 8 + i;
        if (v < VOCAB) {
#pragma unroll
            for (int q = 0; q < 3; q++) {
                int g = lane + 32 * q;
                float lo, hi; upk2(acc[i][q], lo, hi);
                g_proj[(size_t)v * 384 + dg0 + g] = lo + hi + bsh[g];
            }
        }
    }
}

// =====================================================================
// Kernel B: GRU recurrence + on-the-fly mean/max pooling.
// 128 blocks = (direction, batch-pair). 256 threads:
//   bb = tid>>7 (sequence), k = (tid&127)>>1 (h unit), half = tid&1.
// Each thread holds HALF of whh rows {k, 64+k, 128+k} in registers
// (48 ffma2/step), pair-reduces via shfl_xor(1), computes the full
// gate update redundantly. ONE __syncthreads per step, double-buffered h.
// Input projections gathered from g_proj via token id (L2-resident).
// =====================================================================
__global__ void __launch_bounds__(256) kB(
    const int*   __restrict__ tokens,
    const float* __restrict__ whh_f, const float* __restrict__ bhh_f,
    const float* __restrict__ whh_b, const float* __restrict__ bhh_b)
{
    __shared__ __align__(16) float h_sh[2][2][64];   // [buf][bb][k]

    const int tid  = threadIdx.x;
    const int bb   = tid >> 7;
    const int r    = tid & 127;
    const int k    = r >> 1;
    const int half = r & 1;
    const int d    = blockIdx.x >> 6;
    const int pair = blockIdx.x & 63;
    const int b    = pair * 2 + bb;

    const float* whh = d ? whh_b : whh_f;
    const float* bhh = d ? bhh_b : bhh_f;

    // register-resident weight halves (cols [half*32, half*32+32))
    ull wr[16], wz[16], wn[16];
    {
        const ull* pr = (const ull*)(whh + (size_t)k * 64        + half * 32);
        const ull* pz = (const ull*)(whh + (size_t)(64 + k) * 64 + half * 32);
        const ull* pn = (const ull*)(whh + (size_t)(128 + k) * 64 + half * 32);
#pragma unroll
        for (int i = 0; i < 16; i++) { wr[i] = pr[i]; wz[i] = pz[i]; wn[i] = pn[i]; }
    }
    const float br = bhh[k], bz = bhh[64 + k], bn = bhh[128 + k];

    if (tid < 128) h_sh[0][tid >> 6][tid & 63] = 0.0f;

    // token + gate prefetch pipeline (2 deep)
    const int* tokp = tokens + b * T_LEN;
    const float* pb = g_proj + d * 192 + k;
#define TIDX(t) (d ? (T_LEN - 1 - (t)) : (t))
    int tokC;
    float xr0, xz0, xn0, xr1, xz1, xn1;
    {
        int tA = tokp[TIDX(0)], tB = tokp[TIDX(1)];
        size_t oA = (size_t)tA * 384, oB = (size_t)tB * 384;
        xr0 = pb[oA]; xz0 = pb[oA + 64]; xn0 = pb[oA + 128];
        xr1 = pb[oB]; xz1 = pb[oB + 64]; xn1 = pb[oB + 128];
        tokC = tokp[TIDX(2)];
    }

    float sum = 0.0f, mx = -1e30f;
    __syncthreads();

    for (int t = 0; t < T_LEN; t++) {
        const int cur = t & 1, nxt = cur ^ 1;

        // half-dot: whh[{r,z,n} rows, half cols] . h_half
        const ulonglong2* h2 = (const ulonglong2*)&h_sh[cur][bb][half * 32];
        ull ar0 = 0, ar1 = 0, az0 = 0, az1 = 0, an0 = 0, an1 = 0;
#pragma unroll
        for (int i = 0; i < 8; i++) {
            ulonglong2 hv = h2[i];
            ffma2(ar0, wr[2 * i], hv.x); ffma2(ar1, wr[2 * i + 1], hv.y);
            ffma2(az0, wz[2 * i], hv.x); ffma2(az1, wz[2 * i + 1], hv.y);
            ffma2(an0, wn[2 * i], hv.x); ffma2(an1, wn[2 * i + 1], hv.y);
        }
        float lo, hi;
        upk2(fadd2(ar0, ar1), lo, hi); float pr = lo + hi;
        upk2(fadd2(az0, az1), lo, hi); float pz = lo + hi;
        upk2(fadd2(an0, an1), lo, hi); float pn = lo + hi;
        // pair reduction (other half of the dot)
        pr += __shfl_xor_sync(0xffffffffu, pr, 1);
        pz += __shfl_xor_sync(0xffffffffu, pz, 1);
        pn += __shfl_xor_sync(0xffffffffu, pn, 1);

        const float rr = sigm(xr0 + pr + br);
        const float zz = sigm(xz0 + pz + bz);
        const float nn = tanh_fast(xn0 + rr * (pn + bn));
        const float hprev = h_sh[cur][bb][k];
        const float hnew  = fmaf(zz, hprev - nn, nn);   // (1-z)n + z h

        if (half == 0) h_sh[nxt][bb][k] = hnew;
        sum += hnew;
        mx = fmaxf(mx, hnew);

        // rotate prefetch: load gates for t+2, token for t+3 (clamped)
        xr0 = xr1; xz0 = xz1; xn0 = xn1;
        {
            size_t o = (size_t)tokC * 384;
            xr1 = pb[o]; xz1 = pb[o + 64]; xn1 = pb[o + 128];
        }
        {
            int tn = t + 3; if (tn > T_LEN - 1) tn = T_LEN - 1;
            tokC = tokp[TIDX(tn)];
        }
        __syncthreads();
    }
#undef TIDX

    if (half == 0) {
        float* f = g_feats + b * 256;
        if (d == 0) { f[k]      = sum * (1.0f / T_LEN); f[128 + k] = mx; }
        else        { f[64 + k] = sum * (1.0f / T_LEN); f[192 + k] = mx; }
    }
}

// =====================================================================
// Kernel C: classifier head. block = batch row, 64 threads.
// =====================================================================
__global__ void __launch_bounds__(64) kC(
    const float* __restrict__ w1, const float* __restrict__ b1,
    const float* __restrict__ w2, const float* __restrict__ b2,
    float* __restrict__ out)
{
    const int b = blockIdx.x;
    const int j = threadIdx.x;
    __shared__ float hid[64];

    const float* f  = g_feats + b * 256;
    const float* wr = w1 + j * 256;
    float acc = b1[j];
#pragma unroll 8
    for (int i = 0; i < 256; i++) acc += f[i] * wr[i];
    hid[j] = 0.5f * acc * (1.0f + erff(acc * 0.70710678118654752f));
    __syncthreads();

    if (j < NCLS) {
        const float* w2r = w2 + j * 64;
        float o = b2[j];
#pragma unroll
        for (int i = 0; i < 64; i++) o += hid[i] * w2r[i];
        out[b * NCLS + j] = o;
    }
}

// =====================================================================
extern "C" void kernel_launch(void* const* d_in, const int* in_sizes, int n_in,
                              void* d_out, int out_size)
{
    const int*   tokens = (const int*)  d_in[0];
    const float* emb    = (const float*)d_in[1];
    const float* wih_f  = (const float*)d_in[2];
    const float* whh_f  = (const float*)d_in[3];
    const float* bih_f  = (const float*)d_in[4];
    const float* bhh_f  = (const float*)d_in[5];
    const float* wih_b  = (const float*)d_in[6];
    const float* whh_b  = (const float*)d_in[7];
    const float* bih_b  = (const float*)d_in[8];
    const float* bhh_b  = (const float*)d_in[9];
    const float* w1     = (const float*)d_in[10];
    const float* b1     = (const float*)d_in[11];
    const float* w2     = (const float*)d_in[12];
    const float* b2     = (const float*)d_in[13];
    float* out = (float*)d_out;

    const int vtiles = (VOCAB + 63) / 64;   // 786
    kA2<<<dim3(vtiles, 4), 256>>>(emb, wih_f, bih_f, wih_b, bih_b);
    kB<<<128, 256>>>(tokens, whh_f, bhh_f, whh_b, bhh_b);
    kC<<<128, 64>>>(w1, b1, w2, b2, out);
}

// round 3
// speedup vs baseline: 2.0959x; 1.3597x over previous
#include <cuda_runtime.h>
#include <cstdint>
#include <cstddef>

typedef unsigned long long ull;

#define T_LEN 2048
#define B_SZ  128
#define HID   64
#define G3    192
#define NCLS  20
#define VOCAB 50257

// per-vocab input projections: proj[v][d*192+g] = emb[v] . wih_d[g] + bih_d[g]
__device__ float g_proj[(size_t)VOCAB * 384];
// pooled features [b][256] = [mean_f, mean_b, max_f, max_b]
__device__ float g_feats[B_SZ * 256];

// ---------- packed f32x2 + fast-math helpers ----------
__device__ __forceinline__ void ffma2(ull& d, ull a, ull b) {
    asm("fma.rn.f32x2 %0, %1, %2, %0;" : "+l"(d) : "l"(a), "l"(b));
}
__device__ __forceinline__ ull fadd2(ull a, ull b) {
    ull r; asm("add.rn.f32x2 %0, %1, %2;" : "=l"(r) : "l"(a), "l"(b)); return r;
}
__device__ __forceinline__ void upk2(ull v, float& lo, float& hi) {
    asm("mov.b64 {%0, %1}, %2;" : "=f"(lo), "=f"(hi) : "l"(v));
}
__device__ __forceinline__ float ex2a(float x) {
    float r; asm("ex2.approx.f32 %0, %1;" : "=f"(r) : "f"(x)); return r;
}
__device__ __forceinline__ float rcpa(float x) {
    float r; asm("rcp.approx.f32 %0, %1;" : "=f"(r) : "f"(x)); return r;
}
__device__ __forceinline__ float sigm(float p) {
    return rcpa(1.0f + ex2a(-1.4426950408889634f * p));
}
__device__ __forceinline__ float tanh_fast(float x) {
    return 1.0f - 2.0f * rcpa(1.0f + ex2a(2.8853900817779268f * x));
}

// =====================================================================
// Kernel A2: vocab projection table (unchanged from round 2; 102us).
// =====================================================================
__global__ void __launch_bounds__(256) kA2(
    const float* __restrict__ emb,
    const float* __restrict__ wih_f, const float* __restrict__ bih_f,
    const float* __restrict__ wih_b, const float* __restrict__ bih_b)
{
    __shared__ float2 xsh[64][32];   // [v_local][k2]
    __shared__ float2 wsh[32][97];   // [k2][g_local] padded
    __shared__ float  bsh[96];

    const int vt  = blockIdx.x;
    const int dg0 = blockIdx.y * 96;
    const int tid = threadIdx.x;

    for (int idx = tid; idx < 96 * 32; idx += 256) {
        int g = idx >> 5, k2 = idx & 31;
        int dg = dg0 + g;
        const float2* src = (dg < 192) ? (const float2*)(wih_f + dg * 64)
                                       : (const float2*)(wih_b + (dg - 192) * 64);
        wsh[k2][g] = src[k2];
    }
    if (tid < 96) {
        int dg = dg0 + tid;
        bsh[tid] = (dg < 192) ? bih_f[dg] : bih_b[dg - 192];
    }
    for (int idx = tid; idx < 64 * 32; idx += 256) {
        int vl = idx >> 5, k2 = idx & 31;
        int v = vt * 64 + vl; if (v >= VOCAB) v = VOCAB - 1;
        xsh[vl][k2] = ((const float2*)(emb + (size_t)v * 64))[k2];
    }
    __syncthreads();

    const int lane = tid & 31;
    const int wrp  = tid >> 5;

    ull acc[8][3];
#pragma unroll
    for (int i = 0; i < 8; i++)
#pragma unroll
        for (int q = 0; q < 3; q++) acc[i][q] = 0ULL;

    const ull* xp = (const ull*)xsh;
    const ull* wp = (const ull*)wsh;

#pragma unroll 4
    for (int k2 = 0; k2 < 32; k2++) {
        ull xs[8], ws[3];
#pragma unroll
        for (int i = 0; i < 8; i++) xs[i] = xp[(wrp * 8 + i) * 32 + k2];
#pragma unroll
        for (int q = 0; q < 3; q++) ws[q] = wp[k2 * 97 + lane + 32 * q];
#pragma unroll
        for (int i = 0; i < 8; i++)
#pragma unroll
            for (int q = 0; q < 3; q++) ffma2(acc[i][q], xs[i], ws[q]);
    }

#pragma unroll
    for (int i = 0; i < 8; i++) {
        int v = vt * 64 + wrp * 8 + i;
        if (v < VOCAB) {
#pragma unroll
            for (int q = 0; q < 3; q++) {
                int g = lane + 32 * q;
                float lo, hi; upk2(acc[i][q], lo, hi);
                g_proj[(size_t)v * 384 + dg0 + g] = lo + hi + bsh[g];
            }
        }
    }
}

// =====================================================================
// Kernel B v3: GRU recurrence, real 8-deep software pipeline.
// 128 blocks = (direction, batch-pair). 256 threads:
//   bb = tid>>7 (sequence), k = (tid&127)>>1 (h unit), half = tid&1.
// - gate loads go straight into unroll-slot registers, consumed 8 steps
//   later (no MOV-rotation -> true 8-step latency coverage)
// - half0 loads (xr, xn), half1 loads (xz, xn); xr+br / xz+bz folded into
//   the dot partials before the shfl_xor pair-reduce
// - named barrier per sequence (128 threads) instead of block-wide
// - hprev register-resident (update computed redundantly in the pair)
// =====================================================================
__global__ void __launch_bounds__(256) kB(
    const int*   __restrict__ tokens,
    const float* __restrict__ whh_f, const float* __restrict__ bhh_f,
    const float* __restrict__ whh_b, const float* __restrict__ bhh_b)
{
    __shared__ __align__(16) float h_sh[2][2][64];   // [buf][bb][k]

    const int tid  = threadIdx.x;
    const int bb   = tid >> 7;
    const int r    = tid & 127;
    const int k    = r >> 1;
    const int half = r & 1;
    const int d    = blockIdx.x >> 6;
    const int pair = blockIdx.x & 63;
    const int b    = pair * 2 + bb;

    const float* whh = d ? whh_b : whh_f;
    const float* bhh = d ? bhh_b : bhh_f;

    // register-resident weight halves (cols [half*32, half*32+32))
    ull wr[16], wz[16], wn[16];
    {
        const ull* prp = (const ull*)(whh + (size_t)k * 64         + half * 32);
        const ull* pzp = (const ull*)(whh + (size_t)(64 + k) * 64  + half * 32);
        const ull* pnp = (const ull*)(whh + (size_t)(128 + k) * 64 + half * 32);
#pragma unroll
        for (int i = 0; i < 16; i++) { wr[i] = prp[i]; wz[i] = pzp[i]; wn[i] = pnp[i]; }
    }
    const float br = bhh[k], bz = bhh[64 + k], bn = bhh[128 + k];

    if (tid < 128) h_sh[0][tid >> 6][tid & 63] = 0.0f;

    const int* tokp = tokens + b * T_LEN;
#define TIDX(t) (d ? (T_LEN - 1 - (t)) : (t))
    const int offA = d * 192 + (half ? 64 : 0) + k;  // xr (half0) / xz (half1)
    const int offB = d * 192 + 128 + k;              // xn (both)

    // 8-deep pipelines: bufA/bufB[j] hold gates for step t0+j (t0 = loop base)
    float bufA[8], bufB[8];
    int   tbuf[8];
#pragma unroll
    for (int i = 0; i < 8; i++) {
        size_t vo = (size_t)tokp[TIDX(i)] * 384;
        bufA[i] = g_proj[vo + offA];
        bufB[i] = g_proj[vo + offB];
        tbuf[i] = tokp[TIDX(8 + i)];
    }

    float hprev = 0.0f, sum = 0.0f, mx = -1e30f;
    __syncthreads();

    for (int t0 = 0; t0 < T_LEN; t0 += 8) {
#pragma unroll
        for (int j = 0; j < 8; j++) {
            const int t   = t0 + j;
            const int cur = j & 1;          // t0 is even -> (t&1)==(j&1)

            const float a0 = bufA[j];       // gate input for THIS step
            const float b0 = bufB[j];       // xn for this step
            // refill slot j for step t+8; token for step t+16
            {
                size_t vo = (size_t)tbuf[j] * 384;
                bufA[j] = g_proj[vo + offA];
                bufB[j] = g_proj[vo + offB];
                int tn = t + 16; if (tn > T_LEN - 1) tn = T_LEN - 1;
                tbuf[j] = tokp[TIDX(tn)];
            }

            // half-dot: whh[{r,z,n} rows, half cols] . h_half
            const ulonglong2* h2 = (const ulonglong2*)&h_sh[cur][bb][half * 32];
            ull ar0 = 0, ar1 = 0, az0 = 0, az1 = 0, an0 = 0, an1 = 0;
#pragma unroll
            for (int i = 0; i < 8; i++) {
                ulonglong2 hv = h2[i];
                ffma2(ar0, wr[2 * i], hv.x); ffma2(ar1, wr[2 * i + 1], hv.y);
                ffma2(az0, wz[2 * i], hv.x); ffma2(az1, wz[2 * i + 1], hv.y);
                ffma2(an0, wn[2 * i], hv.x); ffma2(an1, wn[2 * i + 1], hv.y);
            }
            float lo, hi;
            upk2(fadd2(ar0, ar1), lo, hi); float pr = lo + hi;
            upk2(fadd2(az0, az1), lo, hi); float pz = lo + hi;
            upk2(fadd2(an0, an1), lo, hi); float pn = lo + hi;
            // fold owned gate input + bias before pair-reduce
            pr += (half == 0) ? (a0 + br) : 0.0f;
            pz += (half == 1) ? (a0 + bz) : 0.0f;
            pr += __shfl_xor_sync(0xffffffffu, pr, 1);
            pz += __shfl_xor_sync(0xffffffffu, pz, 1);
            pn += __shfl_xor_sync(0xffffffffu, pn, 1);

            const float R  = sigm(pr);
            const float Z  = sigm(pz);
            const float N  = tanh_fast(b0 + R * (pn + bn));
            const float hn = fmaf(Z, hprev - N, N);     // (1-z)n + z h
            hprev = hn;
            if (half == 0) h_sh[cur ^ 1][bb][k] = hn;
            sum += hn;
            mx = fmaxf(mx, hn);

            // per-sequence named barrier (warps 0-3 -> id 1, warps 4-7 -> id 2)
            asm volatile("bar.sync %0, 128;" :: "r"(bb + 1) : "memory");
        }
    }
#undef TIDX

    if (half == 0) {
        float* f = g_feats + b * 256;
        if (d == 0) { f[k]      = sum * (1.0f / T_LEN); f[128 + k] = mx; }
        else        { f[64 + k] = sum * (1.0f / T_LEN); f[192 + k] = mx; }
    }
}

// =====================================================================
// Kernel C: classifier head. block = batch row, 64 threads.
// =====================================================================
__global__ void __launch_bounds__(64) kC(
    const float* __restrict__ w1, const float* __restrict__ b1,
    const float* __restrict__ w2, const float* __restrict__ b2,
    float* __restrict__ out)
{
    const int b = blockIdx.x;
    const int j = threadIdx.x;
    __shared__ float hid[64];

    const float* f  = g_feats + b * 256;
    const float* wr = w1 + j * 256;
    float acc = b1[j];
#pragma unroll 8
    for (int i = 0; i < 256; i++) acc += f[i] * wr[i];
    hid[j] = 0.5f * acc * (1.0f + erff(acc * 0.70710678118654752f));
    __syncthreads();

    if (j < NCLS) {
        const float* w2r = w2 + j * 64;
        float o = b2[j];
#pragma unroll
        for (int i = 0; i < 64; i++) o += hid[i] * w2r[i];
        out[b * NCLS + j] = o;
    }
}

// =====================================================================
extern "C" void kernel_launch(void* const* d_in, const int* in_sizes, int n_in,
                              void* d_out, int out_size)
{
    const int*   tokens = (const int*)  d_in[0];
    const float* emb    = (const float*)d_in[1];
    const float* wih_f  = (const float*)d_in[2];
    const float* whh_f  = (const float*)d_in[3];
    const float* bih_f  = (const float*)d_in[4];
    const float* bhh_f  = (const float*)d_in[5];
    const float* wih_b  = (const float*)d_in[6];
    const float* whh_b  = (const float*)d_in[7];
    const float* bih_b  = (const float*)d_in[8];
    const float* bhh_b  = (const float*)d_in[9];
    const float* w1     = (const float*)d_in[10];
    const float* b1     = (const float*)d_in[11];
    const float* w2     = (const float*)d_in[12];
    const float* b2     = (const float*)d_in[13];
    float* out = (float*)d_out;

    const int vtiles = (VOCAB + 63) / 64;   // 786
    kA2<<<dim3(vtiles, 4), 256>>>(emb, wih_f, bih_f, wih_b, bih_b);
    kB<<<128, 256>>>(tokens, whh_f, bhh_f, whh_b, bhh_b);
    kC<<<128, 64>>>(w1, b1, w2, b2, out);
}

// round 4
// speedup vs baseline: 2.4383x; 1.1633x over previous
#include <cuda_runtime.h>
#include <cstdint>
#include <cstddef>

typedef unsigned long long ull;

#define T_LEN 2048
#define B_SZ  128
#define HID   64
#define G3    192
#define NCLS  20
#define VOCAB 50257

// per-vocab input projections: proj[v][d*192+g] = emb[v] . wih_d[g] + bih_d[g]
__device__ float g_proj[(size_t)VOCAB * 384];
// pooled features [b][256] = [mean_f, mean_b, max_f, max_b]
__device__ float g_feats[B_SZ * 256];

// ---------- packed f32x2 + fast-math helpers ----------
__device__ __forceinline__ void ffma2(ull& d, ull a, ull b) {
    asm("fma.rn.f32x2 %0, %1, %2, %0;" : "+l"(d) : "l"(a), "l"(b));
}
__device__ __forceinline__ ull fadd2(ull a, ull b) {
    ull r; asm("add.rn.f32x2 %0, %1, %2;" : "=l"(r) : "l"(a), "l"(b)); return r;
}
__device__ __forceinline__ void upk2(ull v, float& lo, float& hi) {
    asm("mov.b64 {%0, %1}, %2;" : "=f"(lo), "=f"(hi) : "l"(v));
}
__device__ __forceinline__ float ex2a(float x) {
    float r; asm("ex2.approx.f32 %0, %1;" : "=f"(r) : "f"(x)); return r;
}
__device__ __forceinline__ float rcpa(float x) {
    float r; asm("rcp.approx.f32 %0, %1;" : "=f"(r) : "f"(x)); return r;
}
__device__ __forceinline__ float tanha(float x) {
    float r; asm("tanh.approx.f32 %0, %1;" : "=f"(r) : "f"(x)); return r;
}
// sigmoid via single-MUFU tanh: sigma(x) = 0.5 + 0.5*tanh(x/2)
__device__ __forceinline__ float sigm_t(float p) {
    return fmaf(tanha(0.5f * p), 0.5f, 0.5f);
}

// =====================================================================
// Kernel A2: vocab projection table (unchanged; ~102us).
// =====================================================================
__global__ void __launch_bounds__(256) kA2(
    const float* __restrict__ emb,
    const float* __restrict__ wih_f, const float* __restrict__ bih_f,
    const float* __restrict__ wih_b, const float* __restrict__ bih_b)
{
    __shared__ float2 xsh[64][32];   // [v_local][k2]
    __shared__ float2 wsh[32][97];   // [k2][g_local] padded
    __shared__ float  bsh[96];

    const int vt  = blockIdx.x;
    const int dg0 = blockIdx.y * 96;
    const int tid = threadIdx.x;

    for (int idx = tid; idx < 96 * 32; idx += 256) {
        int g = idx >> 5, k2 = idx & 31;
        int dg = dg0 + g;
        const float2* src = (dg < 192) ? (const float2*)(wih_f + dg * 64)
                                       : (const float2*)(wih_b + (dg - 192) * 64);
        wsh[k2][g] = src[k2];
    }
    if (tid < 96) {
        int dg = dg0 + tid;
        bsh[tid] = (dg < 192) ? bih_f[dg] : bih_b[dg - 192];
    }
    for (int idx = tid; idx < 64 * 32; idx += 256) {
        int vl = idx >> 5, k2 = idx & 31;
        int v = vt * 64 + vl; if (v >= VOCAB) v = VOCAB - 1;
        xsh[vl][k2] = ((const float2*)(emb + (size_t)v * 64))[k2];
    }
    __syncthreads();

    const int lane = tid & 31;
    const int wrp  = tid >> 5;

    ull acc[8][3];
#pragma unroll
    for (int i = 0; i < 8; i++)
#pragma unroll
        for (int q = 0; q < 3; q++) acc[i][q] = 0ULL;

    const ull* xp = (const ull*)xsh;
    const ull* wp = (const ull*)wsh;

#pragma unroll 4
    for (int k2 = 0; k2 < 32; k2++) {
        ull xs[8], ws[3];
#pragma unroll
        for (int i = 0; i < 8; i++) xs[i] = xp[(wrp * 8 + i) * 32 + k2];
#pragma unroll
        for (int q = 0; q < 3; q++) ws[q] = wp[k2 * 97 + lane + 32 * q];
#pragma unroll
        for (int i = 0; i < 8; i++)
#pragma unroll
            for (int q = 0; q < 3; q++) ffma2(acc[i][q], xs[i], ws[q]);
    }

#pragma unroll
    for (int i = 0; i < 8; i++) {
        int v = vt * 64 + wrp * 8 + i;
        if (v < VOCAB) {
#pragma unroll
            for (int q = 0; q < 3; q++) {
                int g = lane + 32 * q;
                float lo, hi; upk2(acc[i][q], lo, hi);
                g_proj[(size_t)v * 384 + dg0 + g] = lo + hi + bsh[g];
            }
        }
    }
}

// =====================================================================
// Kernel B v4: GRU recurrence. 256 blocks = one (d,b) sequence each,
// 128 threads: k = tid>>1 (h unit), half = tid&1.
// - 8-deep slot-resident LDG pipeline (gates consumed 8 steps after issue)
// - half-dot + shfl_xor(1) pair reduce; br/bz/bn folded pre-shuffle
// - single-MUFU tanh.approx activations (sigmoid via tanh identity)
// - plain __syncthreads (4 warps) per step; double-buffered h in smem
// =====================================================================
__global__ void __launch_bounds__(128) kB(
    const int*   __restrict__ tokens,
    const float* __restrict__ whh_f, const float* __restrict__ bhh_f,
    const float* __restrict__ whh_b, const float* __restrict__ bhh_b)
{
    __shared__ __align__(16) float h_sh[2][64];   // [buf][k]

    const int tid  = threadIdx.x;
    const int k    = tid >> 1;
    const int half = tid & 1;
    const int d    = blockIdx.x >> 7;
    const int b    = blockIdx.x & 127;

    const float* whh = d ? whh_b : whh_f;
    const float* bhh = d ? bhh_b : bhh_f;

    // register-resident weight halves (cols [half*32, half*32+32))
    ull wr[16], wz[16], wn[16];
    {
        const ull* prp = (const ull*)(whh + (size_t)k * 64         + half * 32);
        const ull* pzp = (const ull*)(whh + (size_t)(64 + k) * 64  + half * 32);
        const ull* pnp = (const ull*)(whh + (size_t)(128 + k) * 64 + half * 32);
#pragma unroll
        for (int i = 0; i < 16; i++) { wr[i] = prp[i]; wz[i] = pzp[i]; wn[i] = pnp[i]; }
    }
    const float br = bhh[k], bz = bhh[64 + k], bn = bhh[128 + k];

    if (tid < 64) h_sh[0][tid] = 0.0f;

    const int* tokp = tokens + b * T_LEN;
#define TIDX(t) (d ? (T_LEN - 1 - (t)) : (t))
    const int offA = d * 192 + (half ? 64 : 0) + k;  // xr (half0) / xz (half1)
    const int offB = d * 192 + 128 + k;              // xn (both halves)

    // 8-deep pipelines: bufA/bufB[j] hold gate inputs for step t0+j
    float bufA[8], bufB[8];
    int   tbuf[8];
#pragma unroll
    for (int i = 0; i < 8; i++) {
        size_t vo = (size_t)tokp[TIDX(i)] * 384;
        bufA[i] = g_proj[vo + offA];
        bufB[i] = g_proj[vo + offB];
        tbuf[i] = tokp[TIDX(8 + i)];
    }

    float hprev = 0.0f, sum = 0.0f, mx = -1e30f;
    __syncthreads();

    for (int t0 = 0; t0 < T_LEN; t0 += 8) {
#pragma unroll
        for (int j = 0; j < 8; j++) {
            const int t   = t0 + j;
            const int cur = j & 1;

            const float a0 = bufA[j];       // xr (half0) / xz (half1)
            const float b0 = bufB[j];       // xn
            // refill slot j for step t+8; token for step t+16
            {
                size_t vo = (size_t)tbuf[j] * 384;
                bufA[j] = g_proj[vo + offA];
                bufB[j] = g_proj[vo + offB];
                int tn = t + 16; if (tn > T_LEN - 1) tn = T_LEN - 1;
                tbuf[j] = tokp[TIDX(tn)];
            }

            // half-dot: whh[{r,z,n} rows, half cols] . h_half
            const ulonglong2* h2 = (const ulonglong2*)&h_sh[cur][half * 32];
            ull ar0 = 0, ar1 = 0, az0 = 0, az1 = 0, an0 = 0, an1 = 0;
#pragma unroll
            for (int i = 0; i < 8; i++) {
                ulonglong2 hv = h2[i];
                ffma2(ar0, wr[2 * i], hv.x); ffma2(ar1, wr[2 * i + 1], hv.y);
                ffma2(az0, wz[2 * i], hv.x); ffma2(az1, wz[2 * i + 1], hv.y);
                ffma2(an0, wn[2 * i], hv.x); ffma2(an1, wn[2 * i + 1], hv.y);
            }
            float lo, hi;
            upk2(fadd2(ar0, ar1), lo, hi); float pr = lo + hi;
            upk2(fadd2(az0, az1), lo, hi); float pz = lo + hi;
            upk2(fadd2(an0, an1), lo, hi); float pn = lo + hi;
            // fold owned gate input + biases BEFORE the pair reduce
            pr += (half == 0) ? (a0 + br) : 0.0f;
            pz += (half == 1) ? (a0 + bz) : 0.0f;
            pn += (half == 0) ? bn : 0.0f;
            pr += __shfl_xor_sync(0xffffffffu, pr, 1);
            pz += __shfl_xor_sync(0xffffffffu, pz, 1);
            pn += __shfl_xor_sync(0xffffffffu, pn, 1);

            const float R  = sigm_t(pr);
            const float Z  = sigm_t(pz);
            const float N  = tanha(fmaf(R, pn, b0));
            const float hn = fmaf(Z, hprev - N, N);     // (1-z)n + z h
            hprev = hn;
            if (half == 0) h_sh[cur ^ 1][k] = hn;
            sum += hn;
            mx = fmaxf(mx, hn);

            __syncthreads();
        }
    }
#undef TIDX

    if (half == 0) {
        float* f = g_feats + b * 256;
        if (d == 0) { f[k]      = sum * (1.0f / T_LEN); f[128 + k] = mx; }
        else        { f[64 + k] = sum * (1.0f / T_LEN); f[192 + k] = mx; }
    }
}

// =====================================================================
// Kernel C: classifier head. block = batch row, 64 threads.
// =====================================================================
__global__ void __launch_bounds__(64) kC(
    const float* __restrict__ w1, const float* __restrict__ b1,
    const float* __restrict__ w2, const float* __restrict__ b2,
    float* __restrict__ out)
{
    const int b = blockIdx.x;
    const int j = threadIdx.x;
    __shared__ float hid[64];

    const float* f  = g_feats + b * 256;
    const float* wr = w1 + j * 256;
    float acc = b1[j];
#pragma unroll 8
    for (int i = 0; i < 256; i++) acc += f[i] * wr[i];
    hid[j] = 0.5f * acc * (1.0f + erff(acc * 0.70710678118654752f));
    __syncthreads();

    if (j < NCLS) {
        const float* w2r = w2 + j * 64;
        float o = b2[j];
#pragma unroll
        for (int i = 0; i < 64; i++) o += hid[i] * w2r[i];
        out[b * NCLS + j] = o;
    }
}

// =====================================================================
extern "C" void kernel_launch(void* const* d_in, const int* in_sizes, int n_in,
                              void* d_out, int out_size)
{
    const int*   tokens = (const int*)  d_in[0];
    const float* emb    = (const float*)d_in[1];
    const float* wih_f  = (const float*)d_in[2];
    const float* whh_f  = (const float*)d_in[3];
    const float* bih_f  = (const float*)d_in[4];
    const float* bhh_f  = (const float*)d_in[5];
    const float* wih_b  = (const float*)d_in[6];
    const float* whh_b  = (const float*)d_in[7];
    const float* bih_b  = (const float*)d_in[8];
    const float* bhh_b  = (const float*)d_in[9];
    const float* w1     = (const float*)d_in[10];
    const float* b1     = (const float*)d_in[11];
    const float* w2     = (const float*)d_in[12];
    const float* b2     = (const float*)d_in[13];
    float* out = (float*)d_out;

    const int vtiles = (VOCAB + 63) / 64;   // 786
    kA2<<<dim3(vtiles, 4), 256>>>(emb, wih_f, bih_f, wih_b, bih_b);
    kB<<<256, 128>>>(tokens, whh_f, bhh_f, whh_b, bhh_b);
    kC<<<128, 64>>>(w1, b1, w2, b2, out);
}

// round 5
// speedup vs baseline: 2.5948x; 1.0642x over previous
#include <cuda_runtime.h>
#include <cstdint>
#include <cstddef>

typedef unsigned long long ull;

#define T_LEN 2048
#define B_SZ  128
#define HID   64
#define G3    192
#define NCLS  20
#define VOCAB 50257
#define TPAD  (T_LEN + 32)

// per-vocab input projections WITH folded biases:
//   g_proj[v][d*192+g] = emb[v].wih_d[g] + bih_d[g] + (g<128 ? bhh_d[g] : 0)
__device__ float g_proj[(size_t)VOCAB * 384];
// pre-scaled, pre-reversed, padded token offsets: tok*384 + d*192
__device__ int g_tokoff[2 * B_SZ * TPAD];
// pooled features [b][256] = [mean_f, mean_b, max_f, max_b]
__device__ float g_feats[B_SZ * 256];

// ---------- packed f32x2 + fast-math helpers ----------
__device__ __forceinline__ void ffma2(ull& d, ull a, ull b) {
    asm("fma.rn.f32x2 %0, %1, %2, %0;" : "+l"(d) : "l"(a), "l"(b));
}
__device__ __forceinline__ ull fadd2(ull a, ull b) {
    ull r; asm("add.rn.f32x2 %0, %1, %2;" : "=l"(r) : "l"(a), "l"(b)); return r;
}
__device__ __forceinline__ void upk2(ull v, float& lo, float& hi) {
    asm("mov.b64 {%0, %1}, %2;" : "=f"(lo), "=f"(hi) : "l"(v));
}
__device__ __forceinline__ float tanha(float x) {
    float r; asm("tanh.approx.f32 %0, %1;" : "=f"(r) : "f"(x)); return r;
}
// sigmoid via single-MUFU tanh: sigma(x) = 0.5 + 0.5*tanh(x/2)
__device__ __forceinline__ float sigm_t(float p) {
    return fmaf(tanha(0.5f * p), 0.5f, 0.5f);
}

// =====================================================================
// Kernel T: token offset table. [d][b][t] = tokens[b][TIDX(t)]*384 + d*192,
// time-reversed for d=1, clamped+padded 32 past the end.
// =====================================================================
__global__ void kT(const int* __restrict__ tokens) {
    const int b = blockIdx.x, d = blockIdx.y;
    const int* src = tokens + b * T_LEN;
    int* dst = g_tokoff + (d * B_SZ + b) * TPAD;
    for (int t = threadIdx.x; t < TPAD; t += blockDim.x) {
        int tt = t < T_LEN ? t : T_LEN - 1;
        int idx = d ? (T_LEN - 1 - tt) : tt;
        dst[t] = src[idx] * 384 + d * 192;
    }
}

// =====================================================================
// Kernel A2 v3: vocab projection table, two row-passes for low regs.
// Block: 64 vocab rows x 96 dg columns, 256 threads. Pass p handles
// rows [32p, 32p+32): warp -> 4 rows, lane covers g = lane + 32q, q<3.
// Bias folded: bih + (gate r/z only) bhh.
// =====================================================================
__global__ void __launch_bounds__(256) kA2(
    const float* __restrict__ emb,
    const float* __restrict__ wih_f, const float* __restrict__ bih_f,
    const float* __restrict__ bhh_f,
    const float* __restrict__ wih_b, const float* __restrict__ bih_b,
    const float* __restrict__ bhh_b)
{
    __shared__ float2 xsh[64][32];   // [v_local][k2]
    __shared__ float2 wsh[32][97];   // [k2][g_local] padded
    __shared__ float  bsh[96];

    const int vt  = blockIdx.x;
    const int dg0 = blockIdx.y * 96;
    const int tid = threadIdx.x;

    for (int idx = tid; idx < 96 * 32; idx += 256) {
        int g = idx >> 5, k2 = idx & 31;
        int dg = dg0 + g;
        const float2* src = (dg < 192) ? (const float2*)(wih_f + dg * 64)
                                       : (const float2*)(wih_b + (dg - 192) * 64);
        wsh[k2][g] = src[k2];
    }
    if (tid < 96) {
        int dg = dg0 + tid;
        float bv;
        if (dg < 192) bv = bih_f[dg] + (dg < 128 ? bhh_f[dg] : 0.0f);
        else { int e = dg - 192; bv = bih_b[e] + (e < 128 ? bhh_b[e] : 0.0f); }
        bsh[tid] = bv;
    }
    for (int idx = tid; idx < 64 * 32; idx += 256) {
        int vl = idx >> 5, k2 = idx & 31;
        int v = vt * 64 + vl; if (v >= VOCAB) v = VOCAB - 1;
        xsh[vl][k2] = ((const float2*)(emb + (size_t)v * 64))[k2];
    }
    __syncthreads();

    const int lane = tid & 31;
    const int wrp  = tid >> 5;
    const ull* xp = (const ull*)xsh;
    const ull* wp = (const ull*)wsh;

#pragma unroll
    for (int pass = 0; pass < 2; pass++) {
        const int row0 = pass * 32 + wrp * 4;

        ull acc[4][3];
#pragma unroll
        for (int i = 0; i < 4; i++)
#pragma unroll
            for (int q = 0; q < 3; q++) acc[i][q] = 0ULL;

#pragma unroll 4
        for (int k2 = 0; k2 < 32; k2++) {
            ull xs[4], ws[3];
#pragma unroll
            for (int i = 0; i < 4; i++) xs[i] = xp[(row0 + i) * 32 + k2];
#pragma unroll
            for (int q = 0; q < 3; q++) ws[q] = wp[k2 * 97 + lane + 32 * q];
#pragma unroll
            for (int i = 0; i < 4; i++)
#pragma unroll
                for (int q = 0; q < 3; q++) ffma2(acc[i][q], xs[i], ws[q]);
        }

#pragma unroll
        for (int i = 0; i < 4; i++) {
            int v = vt * 64 + row0 + i;
            if (v < VOCAB) {
#pragma unroll
                for (int q = 0; q < 3; q++) {
                    int g = lane + 32 * q;
                    float lo, hi; upk2(acc[i][q], lo, hi);
                    g_proj[(size_t)v * 384 + dg0 + g] = lo + hi + bsh[g];
                }
            }
        }
    }
}

// =====================================================================
// Kernel B v5: GRU recurrence. 256 blocks = one (d,b) sequence each,
// 128 threads: k = tid>>1 (h unit), half = tid&1.
// - 8-deep slot-resident gate pipeline fed by int4 token-offset fetches
// - biases pre-folded into g_proj (only bhh_n remains, pre-shuffle fold)
// - half-dot + shfl_xor(1) pair reduce; tanh.approx activations
// - one __syncthreads per step; double-buffered h in smem
// =====================================================================
__global__ void __launch_bounds__(128) kB(
    const float* __restrict__ whh_f, const float* __restrict__ bhh_f,
    const float* __restrict__ whh_b, const float* __restrict__ bhh_b)
{
    __shared__ __align__(16) float h_sh[2][64];   // [buf][k]

    const int tid  = threadIdx.x;
    const int k    = tid >> 1;
    const int half = tid & 1;
    const int d    = blockIdx.x >> 7;
    const int b    = blockIdx.x & 127;

    const float* whh = d ? whh_b : whh_f;
    const float* bhh = d ? bhh_b : bhh_f;

    // register-resident weight halves (cols [half*32, half*32+32))
    ull wr[16], wz[16], wn[16];
    {
        const ull* prp = (const ull*)(whh + (size_t)k * 64         + half * 32);
        const ull* pzp = (const ull*)(whh + (size_t)(64 + k) * 64  + half * 32);
        const ull* pnp = (const ull*)(whh + (size_t)(128 + k) * 64 + half * 32);
#pragma unroll
        for (int i = 0; i < 16; i++) { wr[i] = prp[i]; wz[i] = pzp[i]; wn[i] = pnp[i]; }
    }
    const float bn = bhh[128 + k];

    if (tid < 64) h_sh[0][tid] = 0.0f;

    const int4* tq = (const int4*)(g_tokoff + (d * B_SZ + b) * TPAD);
    const float* pA = g_proj + (half ? 64 : 0) + k;  // xr (half0) / xz (half1)
    const float* pB = g_proj + 128 + k;              // xn (both halves)

    // q2/q3 hold offsets for steps [t0+8, t0+16) across the loop
    int4 q0 = tq[0], q1 = tq[1], q2 = tq[2], q3 = tq[3];

    float bufA[8], bufB[8];
    bufA[0] = pA[q0.x]; bufB[0] = pB[q0.x];
    bufA[1] = pA[q0.y]; bufB[1] = pB[q0.y];
    bufA[2] = pA[q0.z]; bufB[2] = pB[q0.z];
    bufA[3] = pA[q0.w]; bufB[3] = pB[q0.w];
    bufA[4] = pA[q1.x]; bufB[4] = pB[q1.x];
    bufA[5] = pA[q1.y]; bufB[5] = pB[q1.y];
    bufA[6] = pA[q1.z]; bufB[6] = pB[q1.z];
    bufA[7] = pA[q1.w]; bufB[7] = pB[q1.w];

    float hprev = 0.0f, sum = 0.0f, mx = -1e30f;
    __syncthreads();

    for (int t0 = 0; t0 < T_LEN; t0 += 8) {
        int4 qn0, qn1;
#pragma unroll
        for (int j = 0; j < 8; j++) {
            const int cur = j & 1;

            const float a0 = bufA[j];       // xr+b (half0) / xz+b (half1)
            const float b0 = bufB[j];       // xn+bih_n
            // fetch next offset quads (for steps t0+16..t0+23)
            if (j == 0) qn0 = tq[(t0 + 16) >> 2];
            if (j == 4) qn1 = tq[(t0 + 20) >> 2];
            // refill slot j for step t0+j+8 using q2/q3
            {
                const int voj = (j == 0) ? q2.x : (j == 1) ? q2.y : (j == 2) ? q2.z :
                                (j == 3) ? q2.w : (j == 4) ? q3.x : (j == 5) ? q3.y :
                                (j == 6) ? q3.z : q3.w;
                bufA[j] = pA[voj];
                bufB[j] = pB[voj];
            }

            // half-dot: whh[{r,z,n} rows, half cols] . h_half
            const ulonglong2* h2 = (const ulonglong2*)&h_sh[cur][half * 32];
            ull ar0 = 0, ar1 = 0, az0 = 0, az1 = 0, an0 = 0, an1 = 0;
#pragma unroll
            for (int i = 0; i < 8; i++) {
                ulonglong2 hv = h2[i];
                ffma2(ar0, wr[2 * i], hv.x); ffma2(ar1, wr[2 * i + 1], hv.y);
                ffma2(az0, wz[2 * i], hv.x); ffma2(az1, wz[2 * i + 1], hv.y);
                ffma2(an0, wn[2 * i], hv.x); ffma2(an1, wn[2 * i + 1], hv.y);
            }
            float lo, hi;
            upk2(fadd2(ar0, ar1), lo, hi); float pr = lo + hi;
            upk2(fadd2(az0, az1), lo, hi); float pz = lo + hi;
            upk2(fadd2(an0, an1), lo, hi); float pn = lo + hi;
            // fold owned gate input / bhh_n BEFORE the pair reduce
            pr += (half == 0) ? a0 : 0.0f;
            pz += (half == 1) ? a0 : 0.0f;
            pn += (half == 0) ? bn : 0.0f;
            pr += __shfl_xor_sync(0xffffffffu, pr, 1);
            pz += __shfl_xor_sync(0xffffffffu, pz, 1);
            pn += __shfl_xor_sync(0xffffffffu, pn, 1);

            const float R  = sigm_t(pr);
            const float Z  = sigm_t(pz);
            const float N  = tanha(fmaf(R, pn, b0));
            const float hn = fmaf(Z, hprev - N, N);     // (1-z)n + z h
            hprev = hn;
            if (half == 0) h_sh[cur ^ 1][k] = hn;
            sum += hn;
            mx = fmaxf(mx, hn);

            __syncthreads();
        }
        q2 = qn0; q3 = qn1;
    }

    if (half == 0) {
        float* f = g_feats + b * 256;
        if (d == 0) { f[k]      = sum * (1.0f / T_LEN); f[128 + k] = mx; }
        else        { f[64 + k] = sum * (1.0f / T_LEN); f[192 + k] = mx; }
    }
}

// =====================================================================
// Kernel C: classifier head. block = batch row, 64 threads.
// =====================================================================
__global__ void __launch_bounds__(64) kC(
    const float* __restrict__ w1, const float* __restrict__ b1,
    const float* __restrict__ w2, const float* __restrict__ b2,
    float* __restrict__ out)
{
    const int b = blockIdx.x;
    const int j = threadIdx.x;
    __shared__ float hid[64];

    const float* f  = g_feats + b * 256;
    const float* wr = w1 + j * 256;
    float acc = b1[j];
#pragma unroll 8
    for (int i = 0; i < 256; i++) acc += f[i] * wr[i];
    hid[j] = 0.5f * acc * (1.0f + erff(acc * 0.70710678118654752f));
    __syncthreads();

    if (j < NCLS) {
        const float* w2r = w2 + j * 64;
        float o = b2[j];
#pragma unroll
        for (int i = 0; i < 64; i++) o += hid[i] * w2r[i];
        out[b * NCLS + j] = o;
    }
}

// =====================================================================
extern "C" void kernel_launch(void* const* d_in, const int* in_sizes, int n_in,
                              void* d_out, int out_size)
{
    const int*   tokens = (const int*)  d_in[0];
    const float* emb    = (const float*)d_in[1];
    const float* wih_f  = (const float*)d_in[2];
    const float* whh_f  = (const float*)d_in[3];
    const float* bih_f  = (const float*)d_in[4];
    const float* bhh_f  = (const float*)d_in[5];
    const float* wih_b  = (const float*)d_in[6];
    const float* whh_b  = (const float*)d_in[7];
    const float* bih_b  = (const float*)d_in[8];
    const float* bhh_b  = (const float*)d_in[9];
    const float* w1     = (const float*)d_in[10];
    const float* b1     = (const float*)d_in[11];
    const float* w2     = (const float*)d_in[12];
    const float* b2     = (const float*)d_in[13];
    float* out = (float*)d_out;

    kT<<<dim3(B_SZ, 2), 256>>>(tokens);
    const int vtiles = (VOCAB + 63) / 64;   // 786
    kA2<<<dim3(vtiles, 4), 256>>>(emb, wih_f, bih_f, bhh_f, wih_b, bih_b, bhh_b);
    kB<<<256, 128>>>(whh_f, bhh_f, whh_b, bhh_b);
    kC<<<128, 64>>>(w1, b1, w2, b2, out);
}